// round 7
// baseline (speedup 1.0000x reference)
#include <cuda_runtime.h>
#include <cstdint>

#define BATCH   16
#define NANCH   25200
#define NCH     85
#define NCLS    80
#define TOPK    1024
#define MAXDET  300
#define CONF_THR 0.6f
#define IOU_THR  0.45f
#define OFFS     4096.0f
#define NBINS    4096
#define APB      128          // anchors per block in k_score

// ---------------- static device scratch (no allocations allowed) ----------------
__device__ float         g_score[BATCH * NANCH];
__device__ unsigned char g_cls[BATCH * NANCH];
__device__ int           g_topk_idx[BATCH * TOPK];
__device__ float         g_topk_score[BATCH * TOPK];
__device__ float4        g_nmsbox[BATCH * TOPK];
__device__ __align__(16) unsigned int g_mask[BATCH * TOPK * 32];

// ---------------- K1: smem-tiled score / class (thread per anchor) --------------
__global__ void k_score(const float* __restrict__ pred) {
    __shared__ float sp[APB * NCH];            // 43520 B
    int b  = blockIdx.y;
    int a0 = blockIdx.x * APB;
    int tid = threadIdx.x;                     // 256 threads
    int cnt = min(APB, NANCH - a0);            // 128 or 112; both %4==0
    int n4  = (cnt * NCH) >> 2;                // float4 count (divisible)

    const float4* src = (const float4*)(pred + ((size_t)b * NANCH + a0) * NCH);
    float4* dst = (float4*)sp;
    for (int i = tid; i < n4; i += 256) dst[i] = src[i];
    __syncthreads();

    if (tid < cnt) {
        const float* row = sp + tid * NCH;
        float obj = row[4];
        float best = -2.0f; int bidx = 0;
        #pragma unroll 8
        for (int j = 0; j < NCLS; j++) {
            float p = __fmul_rn(obj, row[5 + j]);
            if (p > best) { best = p; bidx = j; }   // strict > = first max (jnp.argmax)
        }
        bool valid = (obj > CONF_THR) && (best > CONF_THR);
        int ga = b * NANCH + a0 + tid;
        g_score[ga] = valid ? best : -1.0f;
        g_cls[ga]   = (unsigned char)bidx;
    }
}

// ---------------- K2: per-image exact top-1024 via histogram + bitonic sort -----
__global__ void __launch_bounds__(1024) k_select(const float* __restrict__ pred) {
    int b   = blockIdx.x;
    int tid = threadIdx.x;                 // 1024 threads
    __shared__ int hist[NBINS];
    __shared__ unsigned long long sbuf[2 * TOPK];
    __shared__ int partial[1024];
    __shared__ int sup[32];
    __shared__ int sh_T;
    __shared__ int counter;

    for (int i = tid; i < NBINS; i += 1024) hist[i] = 0;
    if (tid == 0) counter = 0;
    __syncthreads();

    const float* sc = g_score + (size_t)b * NANCH;
    const float kBinScale = (float)NBINS / 0.4f;

    for (int i = tid; i < NANCH; i += 1024) {
        float s = sc[i];
        if (s > CONF_THR) {
            int bin = (int)((s - CONF_THR) * kBinScale);
            bin = min(max(bin, 0), NBINS - 1);
            atomicAdd(&hist[bin], 1);
        }
    }
    __syncthreads();

    int ps = 0;
    #pragma unroll
    for (int k = 0; k < 4; k++) ps += hist[4 * tid + k];
    partial[tid] = ps;
    __syncthreads();

    if (tid < 32) {
        int s = 0;
        for (int g = 0; g < 32; g++) s += partial[32 * tid + g];
        sup[tid] = s;
        __syncwarp();
        if (tid == 0) {
            int acc = 0, T = 0, l;
            for (l = 31; l >= 0; l--) { if (acc + sup[l] >= TOPK) break; acc += sup[l]; }
            if (l >= 0) {
                int g;
                for (g = 31; g >= 0; g--) { int v = partial[32 * l + g]; if (acc + v >= TOPK) break; acc += v; }
                if (g < 0) g = 0;
                int bb;
                for (bb = 3; bb >= 0; bb--) { int v = hist[4 * (32 * l + g) + bb]; if (acc + v >= TOPK) break; acc += v; }
                if (bb < 0) bb = 0;
                T = 4 * (32 * l + g) + bb;
            }
            sh_T = T;
        }
    }
    __syncthreads();
    int T = sh_T;

    for (int i = tid; i < NANCH; i += 1024) {
        float s = sc[i];
        if (s > CONF_THR) {
            int bin = (int)((s - CONF_THR) * kBinScale);
            bin = min(max(bin, 0), NBINS - 1);
            if (bin >= T) {
                int pos = atomicAdd(&counter, 1);
                if (pos < 2 * TOPK) {
                    unsigned int u = __float_as_uint(s) ^ 0x80000000u;  // order-preserving
                    sbuf[pos] = (((unsigned long long)(~u)) << 32) | (unsigned int)i;
                }
            }
        }
    }
    __syncthreads();
    int M = min(counter, 2 * TOPK);
    for (int i = tid; i < 2 * TOPK; i += 1024)
        if (i >= M) sbuf[i] = 0xFFFFFFFFFFFFFFFFull;
    __syncthreads();

    // bitonic sort ascending: primary ~score_bits (=> score descending), ties idx ascending
    for (int k = 2; k <= 2 * TOPK; k <<= 1) {
        for (int j = k >> 1; j > 0; j >>= 1) {
            for (int e = tid; e < 2 * TOPK; e += 1024) {
                int partner = e ^ j;
                if (partner > e) {
                    bool asc = ((e & k) == 0);
                    unsigned long long a = sbuf[e], c = sbuf[partner];
                    if ((a > c) == asc) { sbuf[e] = c; sbuf[partner] = a; }
                }
            }
            __syncthreads();
        }
    }

    // emit top-1024: idx, score, class-offset nms box
    if (tid < TOPK) {
        int slot = b * TOPK + tid;
        if (tid < M) {
            unsigned long long key = sbuf[tid];
            int idx = (int)(key & 0xFFFFFFFFu);
            unsigned int u = ~((unsigned int)(key >> 32));
            float s = __uint_as_float(u ^ 0x80000000u);
            g_topk_score[slot] = s;
            g_topk_idx[slot]   = idx;
            const float* p = pred + ((size_t)b * NANCH + idx) * NCH;
            float cx = p[0], cy = p[1], w = p[2], h = p[3];
            float hw = __fmul_rn(w, 0.5f), hh = __fmul_rn(h, 0.5f);
            float x1 = __fsub_rn(cx, hw), y1 = __fsub_rn(cy, hh);
            float x2 = __fadd_rn(cx, hw), y2 = __fadd_rn(cy, hh);
            float off = __fmul_rn((float)g_cls[(size_t)b * NANCH + idx], OFFS);
            g_nmsbox[slot] = make_float4(__fadd_rn(x1, off), __fadd_rn(y1, off),
                                         __fadd_rn(x2, off), __fadd_rn(y2, off));
        } else {
            g_topk_score[slot] = -1.0f;
            g_topk_idx[slot]   = 0;
            float far = -1.0e9f - (float)tid * 16.0f;   // inert: never kept, never suppresses
            g_nmsbox[slot] = make_float4(far, far, far + 1.0f, far + 1.0f);
        }
    }
}

// ---------------- K3: suppression bitmask; div only when inter > 0 -------------
__global__ void __launch_bounds__(1024) k_mask() {
    int b = blockIdx.x, q = blockIdx.y;     // q in [0,8): column eighth (128 cols)
    int i = threadIdx.x;                    // 1024 threads, one row each
    __shared__ float4 boxes[TOPK];
    __shared__ float  areas[TOPK];
    for (int t = threadIdx.x; t < TOPK; t += 1024) {
        float4 v = g_nmsbox[b * TOPK + t];
        boxes[t] = v;
        areas[t] = __fmul_rn(__fsub_rn(v.z, v.x), __fsub_rn(v.w, v.y));
    }
    __syncthreads();

    float4 bi = boxes[i];
    float area_i = areas[i];
    int j0 = q * 128;
    #pragma unroll
    for (int w = 0; w < 4; w++) {
        unsigned int m = 0;
        #pragma unroll 4
        for (int t = 0; t < 32; t++) {
            int j = j0 + w * 32 + t;
            if (j > i) {
                float4 bj = boxes[j];
                float ltx = fmaxf(bi.x, bj.x), lty = fmaxf(bi.y, bj.y);
                float rbx = fminf(bi.z, bj.z), rby = fminf(bi.w, bj.w);
                float wx = fmaxf(__fsub_rn(rbx, ltx), 0.0f);
                float wy = fmaxf(__fsub_rn(rby, lty), 0.0f);
                float inter = __fmul_rn(wx, wy);
                if (inter > 0.0f) {         // inter==0 -> iou==+0, never > 0.45
                    float denom = __fadd_rn(__fsub_rn(__fadd_rn(area_i, areas[j]), inter), 1e-9f);
                    float iou = inter / denom;
                    if (iou > IOU_THR) m |= (1u << t);
                }
            }
        }
        g_mask[((size_t)b * TOPK + i) * 32 + q * 4 + w] = m;
    }
}

// ---------------- K4: full-mask smem + ffs walk (smem-resident removed set) -----
__global__ void __launch_bounds__(1024) k_out(const float* __restrict__ pred,
                                              const float* __restrict__ logits,
                                              float* __restrict__ out) {
    extern __shared__ unsigned char dyn[];
    unsigned long long* s_mask = (unsigned long long*)dyn;          // TOPK*16 u64 = 128 KB
    float* s_score = (float*)(dyn + TOPK * 16 * sizeof(unsigned long long)); // 4 KB
    __shared__ unsigned long long s_rem[16];
    __shared__ int sel[MAXDET];
    __shared__ int sh_count;

    int b   = blockIdx.x;
    int tid = threadIdx.x;                  // 1024 threads

    float myscore = g_topk_score[b * TOPK + tid];
    s_score[tid] = myscore;
    if (tid < 16) s_rem[tid] = 0ull;

    // stage entire mask: 8192 ulonglong2 -> 8 per thread, coalesced
    const ulonglong2* gm = (const ulonglong2*)(g_mask + (size_t)b * TOPK * 32);
    ulonglong2* sm2 = (ulonglong2*)s_mask;
    #pragma unroll
    for (int t = 0; t < 8; t++) sm2[t * 1024 + tid] = gm[t * 1024 + tid];

    // validity is a prefix (scores sorted desc): nv = number of valid entries
    int nv = __syncthreads_count(myscore > CONF_THR);

    if (tid == 0) {
        int count = 0;
        #pragma unroll 1
        for (int w = 0; w < 16; w++) {
            int base = w * 64;
            if (base >= nv || count == MAXDET) break;
            unsigned long long valid = (nv - base >= 64)
                ? 0xFFFFFFFFFFFFFFFFull
                : ((1ull << (nv - base)) - 1ull);
            unsigned long long cur  = s_rem[w];        // future keeps already folded in
            unsigned long long todo = valid & ~cur;
            while (todo) {
                int bit = __ffsll((long long)todo) - 1;
                int i = base + bit;
                sel[count] = i;
                count++;
                if (count == MAXDET) break;
                const unsigned long long* mrow = s_mask + (size_t)i * 16;
                cur |= mrow[w];                        // chain: 1 LDS + OR
                #pragma unroll 1
                for (int k = w + 1; k < 16; k++)       // off-chain, pipelined RMWs
                    s_rem[k] |= mrow[k];
                todo &= ~(1ull << bit);
                todo &= ~cur;
            }
        }
        sh_count = count;
    }
    __syncthreads();
    int count = sh_count;

    float* det  = out;                                      // [B,300,6]
    float* vout = out + BATCH * MAXDET * 6;                 // [B,300]
    float* lout = vout + BATCH * MAXDET;                    // [B,300,80]

    for (int s = tid; s < MAXDET; s += 1024) {
        float d0 = 0, d1 = 0, d2 = 0, d3 = 0, d4 = 0, d5 = 0, v = 0;
        if (s < count) {
            int i   = sel[s];
            int idx = g_topk_idx[b * TOPK + i];
            const float* p = pred + ((size_t)b * NANCH + idx) * NCH;
            float cx = p[0], cy = p[1], w = p[2], h = p[3];
            float hw = __fmul_rn(w, 0.5f), hh = __fmul_rn(h, 0.5f);
            d0 = __fsub_rn(cx, hw); d1 = __fsub_rn(cy, hh);
            d2 = __fadd_rn(cx, hw); d3 = __fadd_rn(cy, hh);
            d4 = s_score[i];
            d5 = (float)g_cls[(size_t)b * NANCH + idx];
            v = 1.0f;
        }
        float* dr = det + ((size_t)b * MAXDET + s) * 6;
        dr[0] = d0; dr[1] = d1; dr[2] = d2; dr[3] = d3; dr[4] = d4; dr[5] = d5;
        vout[b * MAXDET + s] = v;
    }

    for (int e = tid; e < MAXDET * NCLS; e += 1024) {
        int s = e / NCLS, c = e % NCLS;
        float v = 0.0f;
        if (s < count) {
            int i   = sel[s];
            int idx = g_topk_idx[b * TOPK + i];
            v = logits[((size_t)b * NANCH + idx) * NCLS + c];
        }
        lout[((size_t)b * MAXDET + s) * NCLS + c] = v;
    }
}

// ---------------- launch --------------------------------------------------------
extern "C" void kernel_launch(void* const* d_in, const int* in_sizes, int n_in,
                              void* d_out, int out_size) {
    (void)in_sizes; (void)n_in; (void)out_size;
    const float* pred   = (const float*)d_in[0];
    const float* logits = (const float*)d_in[1];
    float* out = (float*)d_out;

    const int KOUT_SMEM = TOPK * 16 * (int)sizeof(unsigned long long) + TOPK * (int)sizeof(float);
    cudaFuncSetAttribute(k_out, cudaFuncAttributeMaxDynamicSharedMemorySize, KOUT_SMEM);

    int nxblocks = (NANCH + APB - 1) / APB;          // 197
    k_score<<<dim3(nxblocks, BATCH), 256>>>(pred);
    k_select<<<BATCH, 1024>>>(pred);
    k_mask<<<dim3(BATCH, 8), 1024>>>();
    k_out<<<BATCH, 1024, KOUT_SMEM>>>(pred, logits, out);
}

// round 8
// speedup vs baseline: 1.9428x; 1.9428x over previous
#include <cuda_runtime.h>
#include <cstdint>

#define BATCH   16
#define NANCH   25200
#define NCH     85
#define NCLS    80
#define TOPK    1024
#define MAXDET  300
#define CONF_THR 0.6f
#define IOU_THR  0.45f
#define OFFS     4096.0f
#define NBINS    4096
#define APB      128          // anchors per block in k_score

// ---------------- static device scratch (no allocations allowed) ----------------
__device__ float         g_score[BATCH * NANCH];
__device__ unsigned char g_cls[BATCH * NANCH];
__device__ int           g_topk_idx[BATCH * TOPK];
__device__ float         g_topk_score[BATCH * TOPK];
__device__ float4        g_nmsbox[BATCH * TOPK];
__device__ __align__(16) unsigned int g_mask[BATCH * TOPK * 32];

// ---------------- K1: smem-tiled score / class (thread per anchor) --------------
__global__ void k_score(const float* __restrict__ pred) {
    __shared__ float sp[APB * NCH];            // 43520 B
    int b  = blockIdx.y;
    int a0 = blockIdx.x * APB;
    int tid = threadIdx.x;                     // 256 threads
    int cnt = min(APB, NANCH - a0);            // 128 or 112; both %4==0
    int n4  = (cnt * NCH) >> 2;                // float4 count (divisible)

    const float4* src = (const float4*)(pred + ((size_t)b * NANCH + a0) * NCH);
    float4* dst = (float4*)sp;
    for (int i = tid; i < n4; i += 256) dst[i] = src[i];
    __syncthreads();

    if (tid < cnt) {
        const float* row = sp + tid * NCH;
        float obj = row[4];
        float best = -2.0f; int bidx = 0;
        #pragma unroll 8
        for (int j = 0; j < NCLS; j++) {
            float p = __fmul_rn(obj, row[5 + j]);
            if (p > best) { best = p; bidx = j; }   // strict > = first max (jnp.argmax)
        }
        bool valid = (obj > CONF_THR) && (best > CONF_THR);
        int ga = b * NANCH + a0 + tid;
        g_score[ga] = valid ? best : -1.0f;
        g_cls[ga]   = (unsigned char)bidx;
    }
}

// ---------------- K2: per-image exact top-1024 via histogram + bitonic sort -----
__global__ void k_select(const float* __restrict__ pred) {
    int b   = blockIdx.x;
    int tid = threadIdx.x;                 // 1024 threads
    __shared__ int hist[NBINS];
    __shared__ unsigned long long sbuf[2 * TOPK];
    __shared__ int partial[1024];
    __shared__ int sup[32];
    __shared__ int sh_T;
    __shared__ int counter;

    for (int i = tid; i < NBINS; i += 1024) hist[i] = 0;
    if (tid == 0) counter = 0;
    __syncthreads();

    const float* sc = g_score + (size_t)b * NANCH;
    const float kBinScale = (float)NBINS / 0.4f;

    for (int i = tid; i < NANCH; i += 1024) {
        float s = sc[i];
        if (s > CONF_THR) {
            int bin = (int)((s - CONF_THR) * kBinScale);
            bin = min(max(bin, 0), NBINS - 1);
            atomicAdd(&hist[bin], 1);
        }
    }
    __syncthreads();

    int ps = 0;
    #pragma unroll
    for (int k = 0; k < 4; k++) ps += hist[4 * tid + k];
    partial[tid] = ps;
    __syncthreads();

    if (tid < 32) {
        int s = 0;
        for (int g = 0; g < 32; g++) s += partial[32 * tid + g];
        sup[tid] = s;
        __syncwarp();
        if (tid == 0) {
            int acc = 0, T = 0, l;
            for (l = 31; l >= 0; l--) { if (acc + sup[l] >= TOPK) break; acc += sup[l]; }
            if (l >= 0) {
                int g;
                for (g = 31; g >= 0; g--) { int v = partial[32 * l + g]; if (acc + v >= TOPK) break; acc += v; }
                if (g < 0) g = 0;
                int bb;
                for (bb = 3; bb >= 0; bb--) { int v = hist[4 * (32 * l + g) + bb]; if (acc + v >= TOPK) break; acc += v; }
                if (bb < 0) bb = 0;
                T = 4 * (32 * l + g) + bb;
            }
            sh_T = T;
        }
    }
    __syncthreads();
    int T = sh_T;

    for (int i = tid; i < NANCH; i += 1024) {
        float s = sc[i];
        if (s > CONF_THR) {
            int bin = (int)((s - CONF_THR) * kBinScale);
            bin = min(max(bin, 0), NBINS - 1);
            if (bin >= T) {
                int pos = atomicAdd(&counter, 1);
                if (pos < 2 * TOPK) {
                    unsigned int u = __float_as_uint(s) ^ 0x80000000u;  // order-preserving
                    sbuf[pos] = (((unsigned long long)(~u)) << 32) | (unsigned int)i;
                }
            }
        }
    }
    __syncthreads();
    int M = min(counter, 2 * TOPK);
    for (int i = tid; i < 2 * TOPK; i += 1024)
        if (i >= M) sbuf[i] = 0xFFFFFFFFFFFFFFFFull;
    __syncthreads();

    // bitonic sort ascending: primary ~score_bits (=> score descending), ties idx ascending
    for (int k = 2; k <= 2 * TOPK; k <<= 1) {
        for (int j = k >> 1; j > 0; j >>= 1) {
            for (int e = tid; e < 2 * TOPK; e += 1024) {
                int partner = e ^ j;
                if (partner > e) {
                    bool asc = ((e & k) == 0);
                    unsigned long long a = sbuf[e], c = sbuf[partner];
                    if ((a > c) == asc) { sbuf[e] = c; sbuf[partner] = a; }
                }
            }
            __syncthreads();
        }
    }

    // emit top-1024: idx, score, class-offset nms box
    if (tid < TOPK) {
        int slot = b * TOPK + tid;
        if (tid < M) {
            unsigned long long key = sbuf[tid];
            int idx = (int)(key & 0xFFFFFFFFu);
            unsigned int u = ~((unsigned int)(key >> 32));
            float s = __uint_as_float(u ^ 0x80000000u);
            g_topk_score[slot] = s;
            g_topk_idx[slot]   = idx;
            const float* p = pred + ((size_t)b * NANCH + idx) * NCH;
            float cx = p[0], cy = p[1], w = p[2], h = p[3];
            float hw = __fmul_rn(w, 0.5f), hh = __fmul_rn(h, 0.5f);
            float x1 = __fsub_rn(cx, hw), y1 = __fsub_rn(cy, hh);
            float x2 = __fadd_rn(cx, hw), y2 = __fadd_rn(cy, hh);
            float off = __fmul_rn((float)g_cls[(size_t)b * NANCH + idx], OFFS);
            g_nmsbox[slot] = make_float4(__fadd_rn(x1, off), __fadd_rn(y1, off),
                                         __fadd_rn(x2, off), __fadd_rn(y2, off));
        } else {
            g_topk_score[slot] = -1.0f;
            g_topk_idx[slot]   = 0;
            float far = -1.0e9f - (float)tid * 16.0f;   // inert: never kept, never suppresses
            g_nmsbox[slot] = make_float4(far, far, far + 1.0f, far + 1.0f);
        }
    }
}

// ---------------- K3: suppression bitmask; div only when inter > 0 -------------
__global__ void k_mask() {
    int b = blockIdx.x, q = blockIdx.y;     // q in [0,8): column eighth (128 cols)
    int i = threadIdx.x;                    // 1024 threads, one row each
    __shared__ float4 boxes[TOPK];
    __shared__ float  areas[TOPK];
    for (int t = threadIdx.x; t < TOPK; t += 1024) {
        float4 v = g_nmsbox[b * TOPK + t];
        boxes[t] = v;
        areas[t] = __fmul_rn(__fsub_rn(v.z, v.x), __fsub_rn(v.w, v.y));
    }
    __syncthreads();

    float4 bi = boxes[i];
    float area_i = areas[i];
    int j0 = q * 128;
    #pragma unroll
    for (int w = 0; w < 4; w++) {
        unsigned int m = 0;
        #pragma unroll 4
        for (int t = 0; t < 32; t++) {
            int j = j0 + w * 32 + t;
            if (j > i) {
                float4 bj = boxes[j];
                float ltx = fmaxf(bi.x, bj.x), lty = fmaxf(bi.y, bj.y);
                float rbx = fminf(bi.z, bj.z), rby = fminf(bi.w, bj.w);
                float wx = fmaxf(__fsub_rn(rbx, ltx), 0.0f);
                float wy = fmaxf(__fsub_rn(rby, lty), 0.0f);
                float inter = __fmul_rn(wx, wy);
                if (inter > 0.0f) {         // inter==0 -> iou==+0, never > 0.45
                    float denom = __fadd_rn(__fsub_rn(__fadd_rn(area_i, areas[j]), inter), 1e-9f);
                    float iou = inter / denom;
                    if (iou > IOU_THR) m |= (1u << t);
                }
            }
        }
        g_mask[((size_t)b * TOPK + i) * 32 + q * 4 + w] = m;
    }
}

// ---------------- K4: full-mask smem + warp-cooperative ffs walk ----------------
__global__ void k_out(const float* __restrict__ pred,
                      const float* __restrict__ logits,
                      float* __restrict__ out) {
    extern __shared__ unsigned char dyn[];
    unsigned int* s_mask32 = (unsigned int*)dyn;                    // TOPK*32 u32 = 128 KB
    float* s_score = (float*)(dyn + TOPK * 32 * sizeof(unsigned int)); // 4 KB
    __shared__ int sel[MAXDET];
    __shared__ int sh_count;

    int b   = blockIdx.x;
    int tid = threadIdx.x;                  // 1024 threads

    float myscore = g_topk_score[b * TOPK + tid];
    s_score[tid] = myscore;

    // stage entire mask: 8192 uint4 -> 8 per thread, coalesced
    const uint4* gm = (const uint4*)(g_mask + (size_t)b * TOPK * 32);
    uint4* sm4 = (uint4*)s_mask32;
    #pragma unroll
    for (int t = 0; t < 8; t++) sm4[t * 1024 + tid] = gm[t * 1024 + tid];

    // validity is a prefix (scores sorted desc): nv = number of valid entries
    int nv = __syncthreads_count(myscore > CONF_THR);

    if (tid < 32) {
        // lane L owns removed bits for indices [32L, 32L+32)
        int lane = tid;
        int r = nv - lane * 32;
        unsigned int validw = (r >= 32) ? 0xFFFFFFFFu : ((r <= 0) ? 0u : ((1u << r) - 1u));
        unsigned int rem = 0;
        int count = 0;
        while (count < MAXDET) {
            unsigned int todo = validw & ~rem;
            unsigned int bal = __ballot_sync(0xffffffffu, todo != 0u);
            if (!bal) break;
            int src  = __ffs(bal) - 1;                     // first lane with a candidate
            int myb  = __ffs(todo) - 1;                    // my first candidate bit
            int bit  = __shfl_sync(0xffffffffu, myb, src);
            int i    = src * 32 + bit;
            if (lane == 0) sel[count] = i;
            count++;
            rem |= s_mask32[(size_t)i * 32 + lane];        // parallel OR, one LDS per lane
            if (lane == src) rem |= (1u << bit);           // consume the kept bit
        }
        if (lane == 0) sh_count = count;
    }
    __syncthreads();
    int count = sh_count;

    float* det  = out;                                      // [B,300,6]
    float* vout = out + BATCH * MAXDET * 6;                 // [B,300]
    float* lout = vout + BATCH * MAXDET;                    // [B,300,80]

    for (int s = tid; s < MAXDET; s += 1024) {
        float d0 = 0, d1 = 0, d2 = 0, d3 = 0, d4 = 0, d5 = 0, v = 0;
        if (s < count) {
            int i   = sel[s];
            int idx = g_topk_idx[b * TOPK + i];
            const float* p = pred + ((size_t)b * NANCH + idx) * NCH;
            float cx = p[0], cy = p[1], w = p[2], h = p[3];
            float hw = __fmul_rn(w, 0.5f), hh = __fmul_rn(h, 0.5f);
            d0 = __fsub_rn(cx, hw); d1 = __fsub_rn(cy, hh);
            d2 = __fadd_rn(cx, hw); d3 = __fadd_rn(cy, hh);
            d4 = s_score[i];
            d5 = (float)g_cls[(size_t)b * NANCH + idx];
            v = 1.0f;
        }
        float* dr = det + ((size_t)b * MAXDET + s) * 6;
        dr[0] = d0; dr[1] = d1; dr[2] = d2; dr[3] = d3; dr[4] = d4; dr[5] = d5;
        vout[b * MAXDET + s] = v;
    }

    for (int e = tid; e < MAXDET * NCLS; e += 1024) {
        int s = e / NCLS, c = e % NCLS;
        float v = 0.0f;
        if (s < count) {
            int i   = sel[s];
            int idx = g_topk_idx[b * TOPK + i];
            v = logits[((size_t)b * NANCH + idx) * NCLS + c];
        }
        lout[((size_t)b * MAXDET + s) * NCLS + c] = v;
    }
}

// ---------------- launch --------------------------------------------------------
extern "C" void kernel_launch(void* const* d_in, const int* in_sizes, int n_in,
                              void* d_out, int out_size) {
    (void)in_sizes; (void)n_in; (void)out_size;
    const float* pred   = (const float*)d_in[0];
    const float* logits = (const float*)d_in[1];
    float* out = (float*)d_out;

    const int KOUT_SMEM = TOPK * 32 * (int)sizeof(unsigned int) + TOPK * (int)sizeof(float);
    cudaFuncSetAttribute(k_out, cudaFuncAttributeMaxDynamicSharedMemorySize, KOUT_SMEM);

    int nxblocks = (NANCH + APB - 1) / APB;          // 197
    k_score<<<dim3(nxblocks, BATCH), 256>>>(pred);
    k_select<<<BATCH, 1024>>>(pred);
    k_mask<<<dim3(BATCH, 8), 1024>>>();
    k_out<<<BATCH, 1024, KOUT_SMEM>>>(pred, logits, out);
}

// round 9
// speedup vs baseline: 2.1219x; 1.0922x over previous
#include <cuda_runtime.h>
#include <cstdint>

#define BATCH   16
#define NANCH   25200
#define NCH     85
#define NCLS    80
#define TOPK    1024
#define MAXDET  300
#define CONF_THR 0.6f
#define IOU_THR  0.45f
#define OFFS     4096.0f
#define NBINS    4096
#define APB      256          // anchors per block in k_score

// ---------------- static device scratch (no allocations allowed) ----------------
__device__ float         g_score[BATCH * NANCH];
__device__ unsigned char g_cls[BATCH * NANCH];
__device__ int           g_topk_idx[BATCH * TOPK];
__device__ float         g_topk_score[BATCH * TOPK];
__device__ float4        g_nmsbox[BATCH * TOPK];
__device__ __align__(16) unsigned int g_mask[BATCH * TOPK * 32];

// ---------------- K1: smem-tiled score / class (thread per anchor) --------------
__global__ void k_score(const float* __restrict__ pred) {
    __shared__ float sp[APB * NCH];            // 87040 B
    int b  = blockIdx.y;
    int a0 = blockIdx.x * APB;
    int tid = threadIdx.x;                     // 512 threads
    int cnt = min(APB, NANCH - a0);            // 256 or 112; both %4==0
    int n4  = (cnt * NCH) >> 2;                // float4 count (divisible)

    const float4* src = (const float4*)(pred + ((size_t)b * NANCH + a0) * NCH);
    float4* dst = (float4*)sp;
    for (int i = tid; i < n4; i += 512) dst[i] = src[i];
    __syncthreads();

    for (int a = tid; a < cnt; a += 512) {
        const float* row = sp + a * NCH;
        float obj = row[4];
        float best = -2.0f; int bidx = 0;
        #pragma unroll
        for (int j = 0; j < NCLS; j++) {
            float p = __fmul_rn(obj, row[5 + j]);
            if (p > best) { best = p; bidx = j; }   // strict > = first max (jnp.argmax)
        }
        bool valid = (obj > CONF_THR) && (best > CONF_THR);
        int ga = b * NANCH + a0 + a;
        g_score[ga] = valid ? best : -1.0f;
        g_cls[ga]   = (unsigned char)bidx;
    }
}

// ---- warp-local bitonic stages (j = j0 .. 1) on 2 register keys per lane -------
__device__ __forceinline__ void wl_stages(unsigned long long& a, unsigned long long& b,
                                          int e0, int k, int j0) {
    for (int j = j0; j >= 2; j >>= 1) {
        int jl = j >> 1;
        unsigned long long oa = __shfl_xor_sync(0xffffffffu, a, jl);
        unsigned long long ob = __shfl_xor_sync(0xffffffffu, b, jl);
        bool asc   = ((e0 & k) == 0);
        bool lower = ((e0 & j) == 0);
        bool keepmin = (lower == asc);
        a = keepmin ? (a < oa ? a : oa) : (a > oa ? a : oa);
        b = keepmin ? (b < ob ? b : ob) : (b > ob ? b : ob);
    }
    bool asc = ((e0 & k) == 0);
    if ((a > b) == asc) { unsigned long long t = a; a = b; b = t; }
}

// ---------------- K2: per-image exact top-1024 via histogram + hybrid bitonic ---
__global__ void k_select(const float* __restrict__ pred) {
    int b   = blockIdx.x;
    int tid = threadIdx.x;                 // 1024 threads
    __shared__ int hist[NBINS];
    __shared__ unsigned long long sbuf[2 * TOPK];
    __shared__ int partial[1024];
    __shared__ int sup[32];
    __shared__ int sh_T;
    __shared__ int counter;

    for (int i = tid; i < NBINS; i += 1024) hist[i] = 0;
    if (tid == 0) counter = 0;
    __syncthreads();

    const float* sc = g_score + (size_t)b * NANCH;
    const float kBinScale = (float)NBINS / 0.4f;

    for (int i = tid; i < NANCH; i += 1024) {
        float s = sc[i];
        if (s > CONF_THR) {
            int bin = (int)((s - CONF_THR) * kBinScale);
            bin = min(max(bin, 0), NBINS - 1);
            atomicAdd(&hist[bin], 1);
        }
    }
    __syncthreads();

    int ps = 0;
    #pragma unroll
    for (int k = 0; k < 4; k++) ps += hist[4 * tid + k];
    partial[tid] = ps;
    __syncthreads();

    if (tid < 32) {
        int s = 0;
        for (int g = 0; g < 32; g++) s += partial[32 * tid + g];
        sup[tid] = s;
        __syncwarp();
        if (tid == 0) {
            int acc = 0, T = 0, l;
            for (l = 31; l >= 0; l--) { if (acc + sup[l] >= TOPK) break; acc += sup[l]; }
            if (l >= 0) {
                int g;
                for (g = 31; g >= 0; g--) { int v = partial[32 * l + g]; if (acc + v >= TOPK) break; acc += v; }
                if (g < 0) g = 0;
                int bb;
                for (bb = 3; bb >= 0; bb--) { int v = hist[4 * (32 * l + g) + bb]; if (acc + v >= TOPK) break; acc += v; }
                if (bb < 0) bb = 0;
                T = 4 * (32 * l + g) + bb;
            }
            sh_T = T;
        }
    }
    __syncthreads();
    int T = sh_T;

    for (int i = tid; i < NANCH; i += 1024) {
        float s = sc[i];
        if (s > CONF_THR) {
            int bin = (int)((s - CONF_THR) * kBinScale);
            bin = min(max(bin, 0), NBINS - 1);
            if (bin >= T) {
                int pos = atomicAdd(&counter, 1);
                if (pos < 2 * TOPK) {
                    unsigned int u = __float_as_uint(s) ^ 0x80000000u;  // order-preserving
                    sbuf[pos] = (((unsigned long long)(~u)) << 32) | (unsigned int)i;
                }
            }
        }
    }
    __syncthreads();
    int M = min(counter, 2 * TOPK);
    for (int i = tid; i < 2 * TOPK; i += 1024)
        if (i >= M) sbuf[i] = 0xFFFFFFFFFFFFFFFFull;
    __syncthreads();

    // hybrid bitonic sort ascending over 2048 keys:
    //   primary ~score_bits (=> score descending), ties idx ascending
    {
        int lane = tid & 31, wchunk = tid >> 5;
        int e0 = wchunk * 64 + 2 * lane;           // this lane's even element

        // stages k = 2..64 entirely warp-local
        unsigned long long a = sbuf[e0], bk = sbuf[e0 + 1];
        #pragma unroll
        for (int k = 2; k <= 64; k <<= 1)
            wl_stages(a, bk, e0, k, (k >> 1) > 32 ? 32 : (k >> 1));
        sbuf[e0] = a; sbuf[e0 + 1] = bk;
        __syncthreads();

        // stages k = 128..2048: smem steps for j >= 64, then warp-local j = 32..1
        for (int k = 128; k <= 2048; k <<= 1) {
            for (int j = k >> 1; j >= 64; j >>= 1) {
                #pragma unroll
                for (int e = tid; e < 2 * TOPK; e += 1024) {
                    int partner = e ^ j;
                    if (partner > e) {
                        bool asc = ((e & k) == 0);
                        unsigned long long x = sbuf[e], y = sbuf[partner];
                        if ((x > y) == asc) { sbuf[e] = y; sbuf[partner] = x; }
                    }
                }
                __syncthreads();
            }
            a = sbuf[e0]; bk = sbuf[e0 + 1];
            wl_stages(a, bk, e0, k, 32);
            sbuf[e0] = a; sbuf[e0 + 1] = bk;
            __syncthreads();
        }
    }

    // emit top-1024: idx, score, class-offset nms box
    if (tid < TOPK) {
        int slot = b * TOPK + tid;
        if (tid < M) {
            unsigned long long key = sbuf[tid];
            int idx = (int)(key & 0xFFFFFFFFu);
            unsigned int u = ~((unsigned int)(key >> 32));
            float s = __uint_as_float(u ^ 0x80000000u);
            g_topk_score[slot] = s;
            g_topk_idx[slot]   = idx;
            const float* p = pred + ((size_t)b * NANCH + idx) * NCH;
            float cx = p[0], cy = p[1], w = p[2], h = p[3];
            float hw = __fmul_rn(w, 0.5f), hh = __fmul_rn(h, 0.5f);
            float x1 = __fsub_rn(cx, hw), y1 = __fsub_rn(cy, hh);
            float x2 = __fadd_rn(cx, hw), y2 = __fadd_rn(cy, hh);
            float off = __fmul_rn((float)g_cls[(size_t)b * NANCH + idx], OFFS);
            g_nmsbox[slot] = make_float4(__fadd_rn(x1, off), __fadd_rn(y1, off),
                                         __fadd_rn(x2, off), __fadd_rn(y2, off));
        } else {
            g_topk_score[slot] = -1.0f;
            g_topk_idx[slot]   = 0;
            float far = -1.0e9f - (float)tid * 16.0f;   // inert: never kept, never suppresses
            g_nmsbox[slot] = make_float4(far, far, far + 1.0f, far + 1.0f);
        }
    }
}

// ---------------- K3: suppression bitmask; div only when inter > 0 -------------
__global__ void k_mask() {
    int b = blockIdx.x, q = blockIdx.y;     // q in [0,8): column eighth (128 cols)
    int i = threadIdx.x;                    // 1024 threads, one row each
    __shared__ float4 boxes[TOPK];
    __shared__ float  areas[TOPK];
    for (int t = threadIdx.x; t < TOPK; t += 1024) {
        float4 v = g_nmsbox[b * TOPK + t];
        boxes[t] = v;
        areas[t] = __fmul_rn(__fsub_rn(v.z, v.x), __fsub_rn(v.w, v.y));
    }
    __syncthreads();

    float4 bi = boxes[i];
    float area_i = areas[i];
    int j0 = q * 128;
    #pragma unroll
    for (int w = 0; w < 4; w++) {
        unsigned int m = 0;
        #pragma unroll 4
        for (int t = 0; t < 32; t++) {
            int j = j0 + w * 32 + t;
            if (j > i) {
                float4 bj = boxes[j];
                float ltx = fmaxf(bi.x, bj.x), lty = fmaxf(bi.y, bj.y);
                float rbx = fminf(bi.z, bj.z), rby = fminf(bi.w, bj.w);
                float wx = fmaxf(__fsub_rn(rbx, ltx), 0.0f);
                float wy = fmaxf(__fsub_rn(rby, lty), 0.0f);
                float inter = __fmul_rn(wx, wy);
                if (inter > 0.0f) {         // inter==0 -> iou==+0, never > 0.45
                    float denom = __fadd_rn(__fsub_rn(__fadd_rn(area_i, areas[j]), inter), 1e-9f);
                    float iou = inter / denom;
                    if (iou > IOU_THR) m |= (1u << t);
                }
            }
        }
        g_mask[((size_t)b * TOPK + i) * 32 + q * 4 + w] = m;
    }
}

// ---------------- K4: full-mask smem + REDUX.MIN warp walk ----------------------
__global__ void k_out(const float* __restrict__ pred,
                      const float* __restrict__ logits,
                      float* __restrict__ out) {
    extern __shared__ unsigned char dyn[];
    unsigned int* s_mask32 = (unsigned int*)dyn;                    // TOPK*32 u32 = 128 KB
    float* s_score = (float*)(dyn + TOPK * 32 * sizeof(unsigned int)); // 4 KB
    __shared__ int sel[MAXDET];
    __shared__ int sh_count;

    int b   = blockIdx.x;
    int tid = threadIdx.x;                  // 1024 threads

    float myscore = g_topk_score[b * TOPK + tid];
    s_score[tid] = myscore;

    // stage entire mask: 8192 uint4 -> 8 per thread, coalesced
    const uint4* gm = (const uint4*)(g_mask + (size_t)b * TOPK * 32);
    uint4* sm4 = (uint4*)s_mask32;
    #pragma unroll
    for (int t = 0; t < 8; t++) sm4[t * 1024 + tid] = gm[t * 1024 + tid];

    // validity is a prefix (scores sorted desc): nv = number of valid entries
    int nv = __syncthreads_count(myscore > CONF_THR);

    if (tid < 32) {
        // lane L owns removed bits for indices [32L, 32L+32)
        int lane = tid;
        int r = nv - lane * 32;
        unsigned int validw = (r >= 32) ? 0xFFFFFFFFu : ((r <= 0) ? 0u : ((1u << r) - 1u));
        unsigned int rem = 0;
        int count = 0;
        while (count < MAXDET) {
            unsigned int todo = validw & ~rem;
            unsigned int cand = todo ? ((unsigned int)(lane * 32) + __ffs(todo) - 1u)
                                     : 0xFFFFFFFFu;
            unsigned int i = __reduce_min_sync(0xffffffffu, cand);
            if (i == 0xFFFFFFFFu) break;
            if (lane == 0) sel[count] = (int)i;
            count++;
            rem |= s_mask32[(size_t)i * 32 + lane];        // parallel OR, one LDS per lane
            if ((i >> 5) == (unsigned int)lane) rem |= (1u << (i & 31u));  // consume kept bit
        }
        if (lane == 0) sh_count = count;
    }
    __syncthreads();
    int count = sh_count;

    float* det  = out;                                      // [B,300,6]
    float* vout = out + BATCH * MAXDET * 6;                 // [B,300]
    float* lout = vout + BATCH * MAXDET;                    // [B,300,80]

    for (int s = tid; s < MAXDET; s += 1024) {
        float d0 = 0, d1 = 0, d2 = 0, d3 = 0, d4 = 0, d5 = 0, v = 0;
        if (s < count) {
            int i   = sel[s];
            int idx = g_topk_idx[b * TOPK + i];
            const float* p = pred + ((size_t)b * NANCH + idx) * NCH;
            float cx = p[0], cy = p[1], w = p[2], h = p[3];
            float hw = __fmul_rn(w, 0.5f), hh = __fmul_rn(h, 0.5f);
            d0 = __fsub_rn(cx, hw); d1 = __fsub_rn(cy, hh);
            d2 = __fadd_rn(cx, hw); d3 = __fadd_rn(cy, hh);
            d4 = s_score[i];
            d5 = (float)g_cls[(size_t)b * NANCH + idx];
            v = 1.0f;
        }
        float* dr = det + ((size_t)b * MAXDET + s) * 6;
        dr[0] = d0; dr[1] = d1; dr[2] = d2; dr[3] = d3; dr[4] = d4; dr[5] = d5;
        vout[b * MAXDET + s] = v;
    }

    for (int e = tid; e < MAXDET * NCLS; e += 1024) {
        int s = e / NCLS, c = e % NCLS;
        float v = 0.0f;
        if (s < count) {
            int i   = sel[s];
            int idx = g_topk_idx[b * TOPK + i];
            v = logits[((size_t)b * NANCH + idx) * NCLS + c];
        }
        lout[((size_t)b * MAXDET + s) * NCLS + c] = v;
    }
}

// ---------------- launch --------------------------------------------------------
extern "C" void kernel_launch(void* const* d_in, const int* in_sizes, int n_in,
                              void* d_out, int out_size) {
    (void)in_sizes; (void)n_in; (void)out_size;
    const float* pred   = (const float*)d_in[0];
    const float* logits = (const float*)d_in[1];
    float* out = (float*)d_out;

    const int KOUT_SMEM = TOPK * 32 * (int)sizeof(unsigned int) + TOPK * (int)sizeof(float);
    cudaFuncSetAttribute(k_out, cudaFuncAttributeMaxDynamicSharedMemorySize, KOUT_SMEM);

    int nxblocks = (NANCH + APB - 1) / APB;          // 99
    k_score<<<dim3(nxblocks, BATCH), 512>>>(pred);
    k_select<<<BATCH, 1024>>>(pred);
    k_mask<<<dim3(BATCH, 8), 1024>>>();
    k_out<<<BATCH, 1024, KOUT_SMEM>>>(pred, logits, out);
}